// round 6
// baseline (speedup 1.0000x reference)
#include <cuda_runtime.h>
#include <cstdint>

// ---------------------------------------------------------------------------
// xLSTM cell fused kernel, portable sm_103 path (no "a" features):
//   G[8192,4096] = [x|h] @ [W|U]^T  via mma.sync.m16n8k8.tf32,
//   then sigmoid/tanh gating epilogue, all in one kernel.
//
// R6 change vs R5: fragment-level software pipelining inside each BK=32
// chunk. A fragments double-buffered (prefetch s+1 before s's MMAs), B
// half-chunk preloaded at chunk top, LDSM issued before cp.async prefetch
// after the barrier. Kills the per-s-step LDSM->MMA RAW stall (R5 ncu:
// tensor=69.6%, nothing saturated -> latency-bound).
//
// CTA tile: BM=128 x (4 gates x 32 h-cols); warp tile 64x32 (4g x 8hc);
// acc=64 regs; __launch_bounds__(256,2) -> 2 CTAs/SM, 4 warps/SMSP.
// 3-stage cp.async pipeline (32KB/stage, 96KB/CTA). Grid 2048 = 64m x 32h.
// ---------------------------------------------------------------------------

#define NTHREADS 256
#define STAGES 3
#define A_TILE_BYTES 16384            // 128 rows x 128B (32 tf32)
#define B_TILE_BYTES 16384            // 128 rows (4g x 32hc) x 128B
#define STAGE_BYTES  (A_TILE_BYTES + B_TILE_BYTES)   // 32768
#define SMEM_TOTAL   (STAGES * STAGE_BYTES)          // 98304

#define SWZ(o) ((o) ^ (((o) >> 3) & 0x70))

static __device__ __forceinline__ uint32_t smem_u32(const void* p) {
    uint32_t a;
    asm("{ .reg .u64 t; cvta.to.shared.u64 t, %1; cvt.u32.u64 %0, t; }"
        : "=r"(a) : "l"(p));
    return a;
}

#define CP_ASYNC16(dst, src) \
    asm volatile("cp.async.cg.shared.global [%0], [%1], 16;" :: "r"(dst), "l"(src) : "memory")
#define CP_COMMIT() asm volatile("cp.async.commit_group;" ::: "memory")
#define CP_WAIT1()  asm volatile("cp.async.wait_group 1;" ::: "memory")

#define LDMATRIX_X4(r0, r1, r2, r3, addr) \
    asm volatile("ldmatrix.sync.aligned.m8n8.x4.shared.b16 {%0,%1,%2,%3}, [%4];" \
                 : "=r"(r0), "=r"(r1), "=r"(r2), "=r"(r3) : "r"(addr))

#define MMA_TF32_2(d, a, b0, b1) \
    asm volatile("mma.sync.aligned.m16n8k8.row.col.f32.tf32.tf32.f32 " \
                 "{%0,%1,%2,%3}, {%4,%5,%6,%7}, {%8,%9}, {%0,%1,%2,%3};" \
                 : "+f"((d)[0]), "+f"((d)[1]), "+f"((d)[2]), "+f"((d)[3]) \
                 : "r"((a)[0]), "r"((a)[1]), "r"((a)[2]), "r"((a)[3]), \
                   "r"(b0), "r"(b1))

static __device__ __forceinline__ float sigmoidf_(float v) {
    return 1.0f / (1.0f + __expf(-v));
}
static __device__ __forceinline__ float tanhf_(float v) {
    return 1.0f - 2.0f / (__expf(2.0f * v) + 1.0f);
}

// Load one BK=32 chunk (A tile 128x32 + B tile [4g x 32hc] x 32) into a stage.
static __device__ __forceinline__ void load_chunk32(
    int kc, uint32_t stage_sm,
    const float* __restrict__ x, const float* __restrict__ hprev,
    const float* __restrict__ W, const float* __restrict__ U,
    const uint32_t* dst, const int* srcA, const int* srcB)
{
    const float* asrc = (kc < 32) ? x : hprev;
    const float* bsrc = (kc < 32) ? W : U;
    int k0 = (kc & 31) << 5;
    const float* ap = asrc + k0;
    const float* bp = bsrc + k0;
    uint32_t sB = stage_sm + A_TILE_BYTES;
#pragma unroll
    for (int j = 0; j < 4; j++) CP_ASYNC16(stage_sm + dst[j], ap + srcA[j]);
#pragma unroll
    for (int j = 0; j < 4; j++) CP_ASYNC16(sB + dst[j], bp + srcB[j]);
}

__global__ void __launch_bounds__(NTHREADS, 2) xlstm_tf32_mma_kernel(
    const float* __restrict__ x, const float* __restrict__ hprev,
    const float* __restrict__ cprev,
    const float* __restrict__ W, const float* __restrict__ bW,
    const float* __restrict__ U, const float* __restrict__ bU,
    float* __restrict__ o1, float* __restrict__ o2, float* __restrict__ oc)
{
    extern __shared__ char smem[];
    const uint32_t sbase = smem_u32(smem);

    const int tid  = threadIdx.x;
    const int lane = tid & 31;
    const int warp = tid >> 5;
    const int warp_m = warp >> 2;      // 0..1 : 64 m-rows each
    const int warp_n = warp & 3;       // 0..3 : 8 h-cols each (x4 gates)

    const int bid = blockIdx.x;
    const int m0 = (bid >> 5) << 7;    // 64 m-tiles of 128
    const int h0 = (bid & 31) << 5;    // 32 h-tiles of 32

    // ---- cp.async per-thread offsets (slot j: row r = slot/8, 16B chunk cq) ----
    uint32_t dst[4];
    int srcA[4], srcB[4];
#pragma unroll
    for (int j = 0; j < 4; j++) {
        int slot = tid + j * NTHREADS;       // 0..1023
        int r = slot >> 3, cq = slot & 7;
        dst[j] = SWZ((uint32_t)(r * 128 + cq * 16));
        srcA[j] = (m0 + r) * 1024 + cq * 4;
        int g = r >> 5, hc = r & 31;         // B rows: gate-major [4][32]
        srcB[j] = g * 1048576 + (h0 + hc) * 1024 + cq * 4;
    }

    // ---- ldmatrix per-thread address components ----
    // All rows used by this thread have row%8 == lane%8 -> single xor value.
    const uint32_t xorv = (uint32_t)(lane & 7) << 4;
    // A (m16k8): t0=(r0-7,klo16B) t1=(r8-15,klo) t2=(r0-7,khi) t3=(r8-15,khi)
    uint32_t aOff[4];
#pragma unroll
    for (int mt = 0; mt < 4; mt++)
        aOff[mt] = (uint32_t)(warp_m * 64 + mt * 16 + (lane & 15)) * 128u;
    // pre-xored chunk selectors for the 4 s-steps (k8 each)
    uint32_t aSel[4];
#pragma unroll
    for (int s = 0; s < 4; s++)
        aSel[s] = ((uint32_t)(s * 32) + ((uint32_t)(lane >> 4) << 4)) ^ xorv;
    // B (n8 per gate, one x4 = k16): rows = gate*32 + warp_n*8 + lane%8,
    // lane>>3 selects k-quarter within the 64B half.
    uint32_t bOff[4];
#pragma unroll
    for (int g = 0; g < 4; g++)
        bOff[g] = (uint32_t)(g * 32 + warp_n * 8 + (lane & 7)) * 128u;
    const uint32_t bq0 = (((uint32_t)(lane >> 3) << 4) + 0u)  ^ xorv;   // k 0..15
    const uint32_t bq1 = (((uint32_t)(lane >> 3) << 4) + 64u) ^ xorv;   // k 16..31

    float acc[4][4][4];   // [mt][gate][frag]
#pragma unroll
    for (int mt = 0; mt < 4; mt++)
#pragma unroll
        for (int g = 0; g < 4; g++)
#pragma unroll
            for (int r = 0; r < 4; r++) acc[mt][g][r] = 0.0f;

    // ---- prologue: chunks 0,1 into stages 0,1 ----
    load_chunk32(0, sbase, x, hprev, W, U, dst, srcA, srcB);
    CP_COMMIT();
    load_chunk32(1, sbase + STAGE_BYTES, x, hprev, W, U, dst, srcA, srcB);
    CP_COMMIT();

    // ---- mainloop: 64 BK=32 chunks, 3 stages ----
    int cur = 0, pf = 2;   // stage of chunk kc; stage for chunk kc+2
#pragma unroll 1
    for (int kc = 0; kc < 64; kc++) {
        CP_WAIT1();          // chunk kc resident (kc+1 may still be in flight)
        __syncthreads();     // data visible to all; stage pf free to overwrite

        const uint32_t sA = sbase + (uint32_t)cur * STAGE_BYTES;
        const uint32_t sB = sA + A_TILE_BYTES;

        // restart tensor path first: B half0 (k0..15) + A(s=0)
        uint32_t b[4][4];    // [gate][reg]: {0,1}=k8 lo, {2,3}=k8 hi of the half
        uint32_t a0[4][4], a1[4][4];
#pragma unroll
        for (int g = 0; g < 4; g++)
            LDMATRIX_X4(b[g][0], b[g][1], b[g][2], b[g][3], sB + bOff[g] + bq0);
#pragma unroll
        for (int mt = 0; mt < 4; mt++)
            LDMATRIX_X4(a0[mt][0], a0[mt][1], a0[mt][2], a0[mt][3],
                        sA + aOff[mt] + aSel[0]);

        // then issue next chunk's global loads (non-blocking)
        if (kc + 2 < 64)
            load_chunk32(kc + 2, sbase + (uint32_t)pf * STAGE_BYTES,
                         x, hprev, W, U, dst, srcA, srcB);
        CP_COMMIT();

        // s0: prefetch A(s1), MMA with a0 / b half0-lo
#pragma unroll
        for (int mt = 0; mt < 4; mt++)
            LDMATRIX_X4(a1[mt][0], a1[mt][1], a1[mt][2], a1[mt][3],
                        sA + aOff[mt] + aSel[1]);
#pragma unroll
        for (int mt = 0; mt < 4; mt++)
#pragma unroll
            for (int g = 0; g < 4; g++)
                MMA_TF32_2(acc[mt][g], a0[mt], b[g][0], b[g][1]);

        // s1: prefetch A(s2) into a0, MMA with a1 / b half0-hi
#pragma unroll
        for (int mt = 0; mt < 4; mt++)
            LDMATRIX_X4(a0[mt][0], a0[mt][1], a0[mt][2], a0[mt][3],
                        sA + aOff[mt] + aSel[2]);
#pragma unroll
        for (int mt = 0; mt < 4; mt++)
#pragma unroll
            for (int g = 0; g < 4; g++)
                MMA_TF32_2(acc[mt][g], a1[mt], b[g][2], b[g][3]);

        // reload B half1 (k16..31)
#pragma unroll
        for (int g = 0; g < 4; g++)
            LDMATRIX_X4(b[g][0], b[g][1], b[g][2], b[g][3], sB + bOff[g] + bq1);

        // s2: prefetch A(s3) into a1, MMA with a0 / b half1-lo
#pragma unroll
        for (int mt = 0; mt < 4; mt++)
            LDMATRIX_X4(a1[mt][0], a1[mt][1], a1[mt][2], a1[mt][3],
                        sA + aOff[mt] + aSel[3]);
#pragma unroll
        for (int mt = 0; mt < 4; mt++)
#pragma unroll
            for (int g = 0; g < 4; g++)
                MMA_TF32_2(acc[mt][g], a0[mt], b[g][0], b[g][1]);

        // s3: MMA with a1 / b half1-hi
#pragma unroll
        for (int mt = 0; mt < 4; mt++)
#pragma unroll
            for (int g = 0; g < 4; g++)
                MMA_TF32_2(acc[mt][g], a1[mt], b[g][2], b[g][3]);

        cur = (cur == 2) ? 0 : cur + 1;
        pf  = (pf == 2) ? 0 : pf + 1;
    }

    // ---- epilogue: thread-local (all 4 gates of each (m,h) in this thread) ----
    // C frag: c0=(row l/4, col 2(l%4)); c1=+1col; c2=+8row; c3=+8row+1col
    const int hc0 = h0 + warp_n * 8 + 2 * (lane & 3);

    float bsum[4][2];
#pragma unroll
    for (int g = 0; g < 4; g++)
#pragma unroll
        for (int e = 0; e < 2; e++)
            bsum[g][e] = bW[g * 1024 + hc0 + e] + bU[g * 1024 + hc0 + e];

#pragma unroll
    for (int mt = 0; mt < 4; mt++) {
#pragma unroll
        for (int rh = 0; rh < 2; rh++) {
            int m = m0 + warp_m * 64 + mt * 16 + (lane >> 2) + rh * 8;
            size_t base = (size_t)m * 1024 + hc0;
            float2 cold = *reinterpret_cast<const float2*>(cprev + base);

            float hn[2], cn[2];
#pragma unroll
            for (int e = 0; e < 2; e++) {
                int rr = rh * 2 + e;
                float gi = acc[mt][0][rr] + bsum[0][e];
                float gf = acc[mt][1][rr] + bsum[1][e];
                float go = acc[mt][2][rr] + bsum[2][e];
                float gc = acc[mt][3][rr] + bsum[3][e];
                float iv = sigmoidf_(gi);
                float fv = sigmoidf_(gf);
                float ov = sigmoidf_(go);
                float ch = tanhf_(gc);
                float cold_e = (e == 0) ? cold.x : cold.y;
                float cv = fv * cold_e + iv * ch;
                cn[e] = cv;
                hn[e] = ov * tanhf_(cv);
            }

            float2 hv = make_float2(hn[0], hn[1]);
            *reinterpret_cast<float2*>(o1 + base) = hv;
            if (o2) *reinterpret_cast<float2*>(o2 + base) = hv;
            if (oc) *reinterpret_cast<float2*>(oc + base) = make_float2(cn[0], cn[1]);
        }
    }
}

extern "C" void kernel_launch(void* const* d_in, const int* in_sizes, int n_in,
                              void* d_out, int out_size) {
    const float* x  = (const float*)d_in[0];
    const float* h  = (const float*)d_in[1];
    const float* c  = (const float*)d_in[2];
    const float* W  = (const float*)d_in[3];
    const float* bW = (const float*)d_in[4];
    const float* U  = (const float*)d_in[5];
    const float* bU = (const float*)d_in[6];
    float* out = (float*)d_out;

    const long long BH = 8192LL * 1024LL;
    float* o1 = out;
    float* o2 = nullptr;
    float* oc = nullptr;
    if ((long long)out_size >= 3 * BH) {          // (h_new, h_new, c_new)
        o2 = out + BH;
        oc = out + 2 * BH;
    } else if ((long long)out_size >= 2 * BH) {   // (h_new, c_new)
        oc = out + BH;
    }

    cudaFuncSetAttribute(xlstm_tf32_mma_kernel,
                         cudaFuncAttributeMaxDynamicSharedMemorySize, SMEM_TOTAL);
    xlstm_tf32_mma_kernel<<<2048, NTHREADS, SMEM_TOTAL>>>(x, h, c, W, bW, U, bU, o1, o2, oc);
}

// round 7
// speedup vs baseline: 1.7833x; 1.7833x over previous
#include <cuda_runtime.h>
#include <cuda_fp16.h>
#include <cstdint>

// ---------------------------------------------------------------------------
// xLSTM cell, fused, portable sm_103 path (no "a" features):
//   pass 1: convert x,h,W,U fp32 -> fp16 scratch (static __device__ buffers)
//   pass 2: G[8192,4096] = [x|h] @ [W|U]^T via mma.m16n8k16.f16 (2x tf32 rate,
//           SAME 11-bit mantissa as tf32), fp32 accum, gating epilogue fused.
//
// R7 vs R5/R6: datatype switch tf32 -> fp16 (ceiling ~305 -> ~610 TF/s).
// R6's manual fragment pipelining REGRESSED -> reverted to R5 loop body.
// CTA tile: BM=128 x (4 gates x 32 h-cols); warp tile 64x32 (4g x 8hc);
// BK=64 fp16 per 128B smem row; 3-stage cp.async (32KB/stage, 96KB/CTA);
// __launch_bounds__(256,2) -> 2 CTAs/SM. Grid 2048 = 64m x 32h.
// ---------------------------------------------------------------------------

#define NTHREADS 256
#define STAGES 3
#define A_TILE_BYTES 16384            // 128 rows x 128B (64 fp16)
#define B_TILE_BYTES 16384            // 128 rows (4g x 32hc) x 128B
#define STAGE_BYTES  (A_TILE_BYTES + B_TILE_BYTES)   // 32768
#define SMEM_TOTAL   (STAGES * STAGE_BYTES)          // 98304

#define N_X 8388608                   // 8192*1024
#define N_W 4194304                   // 4*1024*1024

__device__ __align__(16) __half g_x16[N_X];
__device__ __align__(16) __half g_h16[N_X];
__device__ __align__(16) __half g_W16[N_W];
__device__ __align__(16) __half g_U16[N_W];

#define SWZ(o) ((o) ^ (((o) >> 3) & 0x70))

static __device__ __forceinline__ uint32_t smem_u32(const void* p) {
    uint32_t a;
    asm("{ .reg .u64 t; cvta.to.shared.u64 t, %1; cvt.u32.u64 %0, t; }"
        : "=r"(a) : "l"(p));
    return a;
}

#define CP_ASYNC16(dst, src) \
    asm volatile("cp.async.cg.shared.global [%0], [%1], 16;" :: "r"(dst), "l"(src) : "memory")
#define CP_COMMIT() asm volatile("cp.async.commit_group;" ::: "memory")
#define CP_WAIT1()  asm volatile("cp.async.wait_group 1;" ::: "memory")

#define LDMATRIX_X4(r0, r1, r2, r3, addr) \
    asm volatile("ldmatrix.sync.aligned.m8n8.x4.shared.b16 {%0,%1,%2,%3}, [%4];" \
                 : "=r"(r0), "=r"(r1), "=r"(r2), "=r"(r3) : "r"(addr))

#define MMA_F16(d, a, b0, b1) \
    asm volatile("mma.sync.aligned.m16n8k16.row.col.f32.f16.f16.f32 " \
                 "{%0,%1,%2,%3}, {%4,%5,%6,%7}, {%8,%9}, {%0,%1,%2,%3};" \
                 : "+f"((d)[0]), "+f"((d)[1]), "+f"((d)[2]), "+f"((d)[3]) \
                 : "r"((a)[0]), "r"((a)[1]), "r"((a)[2]), "r"((a)[3]), \
                   "r"(b0), "r"(b1))

static __device__ __forceinline__ float sigmoidf_(float v) {
    return 1.0f / (1.0f + __expf(-v));
}
static __device__ __forceinline__ float tanhf_(float v) {
    return 1.0f - 2.0f / (__expf(2.0f * v) + 1.0f);
}

// ---------------- pass 1: fp32 -> fp16 conversion --------------------------
__global__ void __launch_bounds__(256) cvt_f32_to_f16_kernel(
    const float* __restrict__ x, const float* __restrict__ h,
    const float* __restrict__ W, const float* __restrict__ U)
{
    const long long n4x = N_X / 4, n4w = N_W / 4;
    const long long total = 2 * n4x + 2 * n4w;
    const long long stride = (long long)gridDim.x * blockDim.x;
    for (long long i = (long long)blockIdx.x * blockDim.x + threadIdx.x;
         i < total; i += stride) {
        const float* s;
        __half* d;
        long long j;
        if (i < n4x)                { s = x; d = g_x16; j = i; }
        else if (i < 2 * n4x)       { s = h; d = g_h16; j = i - n4x; }
        else if (i < 2 * n4x + n4w) { s = W; d = g_W16; j = i - 2 * n4x; }
        else                        { s = U; d = g_U16; j = i - 2 * n4x - n4w; }
        float4 v = reinterpret_cast<const float4*>(s)[j];
        __half2 lo = __floats2half2_rn(v.x, v.y);
        __half2 hi = __floats2half2_rn(v.z, v.w);
        uint2 u;
        u.x = *reinterpret_cast<uint32_t*>(&lo);
        u.y = *reinterpret_cast<uint32_t*>(&hi);
        reinterpret_cast<uint2*>(d)[j] = u;
    }
}

// Load one BK=64 chunk (A 128x64 fp16 + B [4g x 32hc] x 64 fp16) into a stage.
static __device__ __forceinline__ void load_chunk64(
    int kc, uint32_t stage_sm,
    const uint32_t* dst, const int* srcA, const int* srcB)
{
    const __half* ap = (kc < 16) ? g_x16 : g_h16;
    const __half* bp = (kc < 16) ? g_W16 : g_U16;
    int k0 = (kc & 15) << 6;
    uint32_t sB = stage_sm + A_TILE_BYTES;
#pragma unroll
    for (int j = 0; j < 4; j++) CP_ASYNC16(stage_sm + dst[j], ap + srcA[j] + k0);
#pragma unroll
    for (int j = 0; j < 4; j++) CP_ASYNC16(sB + dst[j], bp + srcB[j] + k0);
}

__global__ void __launch_bounds__(NTHREADS, 2) xlstm_f16_mma_kernel(
    const float* __restrict__ cprev,
    const float* __restrict__ bW, const float* __restrict__ bU,
    float* __restrict__ o1, float* __restrict__ o2, float* __restrict__ oc)
{
    extern __shared__ char smem[];
    const uint32_t sbase = smem_u32(smem);

    const int tid  = threadIdx.x;
    const int lane = tid & 31;
    const int warp = tid >> 5;
    const int warp_m = warp >> 2;      // 0..1 : 64 m-rows each
    const int warp_n = warp & 3;       // 0..3 : 8 h-cols each (x4 gates)

    const int bid = blockIdx.x;
    const int m0 = (bid >> 5) << 7;    // 64 m-tiles of 128
    const int h0 = (bid & 31) << 5;    // 32 h-tiles of 32

    // ---- cp.async per-thread offsets (slot j: row r = slot/8, 16B chunk cq) ----
    // 16B = 8 fp16; a full 128-row tile = 1024 slots = 4 per thread.
    uint32_t dst[4];
    int srcA[4], srcB[4];
#pragma unroll
    for (int j = 0; j < 4; j++) {
        int slot = tid + j * NTHREADS;       // 0..1023
        int r = slot >> 3, cq = slot & 7;
        dst[j] = SWZ((uint32_t)(r * 128 + cq * 16));
        srcA[j] = (m0 + r) * 1024 + cq * 8;
        int g = r >> 5, hc = r & 31;         // B rows: gate-major [4][32]
        srcB[j] = g * 1048576 + (h0 + hc) * 1024 + cq * 8;
    }

    // ---- ldmatrix per-thread address components ----
    // All rows used by this thread have row%8 == lane%8 -> single xor value.
    const uint32_t xorv = (uint32_t)(lane & 7) << 4;
    // A (m16k16 per x4): lanes 0-15 -> rows @ k8-lo chunk, 16-31 -> k8-hi.
    uint32_t aOff[4];
#pragma unroll
    for (int mt = 0; mt < 4; mt++)
        aOff[mt] = (uint32_t)(warp_m * 64 + mt * 16 + (lane & 15)) * 128u;
    // k16 step s (0..3): chunks at s*32 (+16 for hi half)
    uint32_t aSel[4];
#pragma unroll
    for (int s = 0; s < 4; s++)
        aSel[s] = ((uint32_t)(s * 32) + ((uint32_t)(lane >> 4) << 4)) ^ xorv;
    // B (n8 x k32 per x4): rows = gate*32 + warp_n*8 + lane%8,
    // lane>>3 selects the k8 quarter within the 64B half-row.
    uint32_t bOff[4];
#pragma unroll
    for (int g = 0; g < 4; g++)
        bOff[g] = (uint32_t)(g * 32 + warp_n * 8 + (lane & 7)) * 128u;
    uint32_t bSel[2];
#pragma unroll
    for (int kh = 0; kh < 2; kh++)
        bSel[kh] = ((uint32_t)(kh * 64) + ((uint32_t)(lane >> 3) << 4)) ^ xorv;

    float acc[4][4][4];   // [mt][gate][frag]
#pragma unroll
    for (int mt = 0; mt < 4; mt++)
#pragma unroll
        for (int g = 0; g < 4; g++)
#pragma unroll
            for (int r = 0; r < 4; r++) acc[mt][g][r] = 0.0f;

    // ---- prologue: chunks 0,1 into stages 0,1 ----
    load_chunk64(0, sbase, dst, srcA, srcB);
    CP_COMMIT();
    load_chunk64(1, sbase + STAGE_BYTES, dst, srcA, srcB);
    CP_COMMIT();

    // ---- mainloop: 32 BK=64 chunks, 3 stages ----
    int cur = 0, pf = 2;
#pragma unroll 1
    for (int kc = 0; kc < 32; kc++) {
        CP_WAIT1();          // chunk kc resident (kc+1 may still be in flight)
        __syncthreads();     // data visible; stage pf free to overwrite

        if (kc + 2 < 32)
            load_chunk64(kc + 2, sbase + (uint32_t)pf * STAGE_BYTES,
                         dst, srcA, srcB);
        CP_COMMIT();

        const uint32_t sA = sbase + (uint32_t)cur * STAGE_BYTES;
        const uint32_t sB = sA + A_TILE_BYTES;

#pragma unroll
        for (int kh = 0; kh < 2; kh++) {
            uint32_t b[4][4];   // [gate][k8 quarter of this k32 half]
#pragma unroll
            for (int g = 0; g < 4; g++)
                LDMATRIX_X4(b[g][0], b[g][1], b[g][2], b[g][3],
                            sB + bOff[g] + bSel[kh]);
#pragma unroll
            for (int t = 0; t < 2; t++) {     // two k16 steps per half
                const uint32_t aCh = aSel[kh * 2 + t];
                const int bs = t << 1;        // 0 or 2
#pragma unroll
                for (int mt = 0; mt < 4; mt++) {
                    uint32_t a[4];
                    LDMATRIX_X4(a[0], a[1], a[2], a[3], sA + aOff[mt] + aCh);
#pragma unroll
                    for (int g = 0; g < 4; g++)
                        MMA_F16(acc[mt][g], a, b[g][bs], b[g][bs + 1]);
                }
            }
        }

        cur = (cur == 2) ? 0 : cur + 1;
        pf  = (pf == 2) ? 0 : pf + 1;
    }

    // ---- epilogue: thread-local (all 4 gates of each (m,h) in this thread) ----
    // C frag: c0=(row l/4, col 2(l%4)); c1=+1col; c2=+8row; c3=+8row+1col
    const int hc0 = h0 + warp_n * 8 + 2 * (lane & 3);

    float bsum[4][2];
#pragma unroll
    for (int g = 0; g < 4; g++)
#pragma unroll
        for (int e = 0; e < 2; e++)
            bsum[g][e] = bW[g * 1024 + hc0 + e] + bU[g * 1024 + hc0 + e];

#pragma unroll
    for (int mt = 0; mt < 4; mt++) {
#pragma unroll
        for (int rh = 0; rh < 2; rh++) {
            int m = m0 + warp_m * 64 + mt * 16 + (lane >> 2) + rh * 8;
            size_t base = (size_t)m * 1024 + hc0;
            float2 cold = *reinterpret_cast<const float2*>(cprev + base);

            float hn[2], cn[2];
#pragma unroll
            for (int e = 0; e < 2; e++) {
                int rr = rh * 2 + e;
                float gi = acc[mt][0][rr] + bsum[0][e];
                float gf = acc[mt][1][rr] + bsum[1][e];
                float go = acc[mt][2][rr] + bsum[2][e];
                float gc = acc[mt][3][rr] + bsum[3][e];
                float iv = sigmoidf_(gi);
                float fv = sigmoidf_(gf);
                float ov = sigmoidf_(go);
                float ch = tanhf_(gc);
                float cold_e = (e == 0) ? cold.x : cold.y;
                float cv = fv * cold_e + iv * ch;
                cn[e] = cv;
                hn[e] = ov * tanhf_(cv);
            }

            float2 hv = make_float2(hn[0], hn[1]);
            *reinterpret_cast<float2*>(o1 + base) = hv;
            if (o2) *reinterpret_cast<float2*>(o2 + base) = hv;
            if (oc) *reinterpret_cast<float2*>(oc + base) = make_float2(cn[0], cn[1]);
        }
    }
}

extern "C" void kernel_launch(void* const* d_in, const int* in_sizes, int n_in,
                              void* d_out, int out_size) {
    const float* x  = (const float*)d_in[0];
    const float* h  = (const float*)d_in[1];
    const float* c  = (const float*)d_in[2];
    const float* W  = (const float*)d_in[3];
    const float* bW = (const float*)d_in[4];
    const float* U  = (const float*)d_in[5];
    const float* bU = (const float*)d_in[6];
    float* out = (float*)d_out;

    const long long BH = 8192LL * 1024LL;
    float* o1 = out;
    float* o2 = nullptr;
    float* oc = nullptr;
    if ((long long)out_size >= 3 * BH) {          // (h_new, h_new, c_new)
        o2 = out + BH;
        oc = out + 2 * BH;
    } else if ((long long)out_size >= 2 * BH) {   // (h_new, c_new)
        oc = out + BH;
    }

    cvt_f32_to_f16_kernel<<<4096, 256>>>(x, h, W, U);

    cudaFuncSetAttribute(xlstm_f16_mma_kernel,
                         cudaFuncAttributeMaxDynamicSharedMemorySize, SMEM_TOTAL);
    xlstm_f16_mma_kernel<<<2048, NTHREADS, SMEM_TOTAL>>>(c, bW, bU, o1, o2, oc);
}